// round 1
// baseline (speedup 1.0000x reference)
#include <cuda_runtime.h>
#include <cuda_bf16.h>
#include <cstdint>

#define DIM 1024
#define SEQ 2048
#define NHEADS 16
#define HDIM 64

// ---------------------------------------------------------------------------
// Static scratch (allocation-free contract: __device__ globals)
// ---------------------------------------------------------------------------
#define MMAX (2 * SEQ)           // B*L = 4096
__device__ float g_q1[MMAX * DIM];
__device__ float g_k1[MMAX * DIM];
__device__ float g_v1[MMAX * DIM];
__device__ float g_tmp[MMAX * DIM];
__device__ float g_attn[MMAX * DIM];
__device__ float g_norm[MMAX * DIM];
__device__ float g_gp[MMAX * 2 * DIM];

// ---------------------------------------------------------------------------
// GEMM: C[m,n] = act( sum_k A[m,k] * W[n,k] + bias[n] )
// A: MxK row-major, W: NxK row-major (i.e. B^T), C: MxN row-major
// BM=BN=128, BK=16, 256 threads, 8x8 per-thread microtile.
// ACT: 0 = none, 1 = silu
// ---------------------------------------------------------------------------
template<int ACT>
__global__ __launch_bounds__(256)
void gemm128(const float* __restrict__ A, const float* __restrict__ W,
             const float* __restrict__ bias, float* __restrict__ C,
             int M, int N, int K)
{
    constexpr int BM = 128, BN = 128, BK = 16;
    __shared__ float As[BK][BM];
    __shared__ float Bs[BK][BN];

    const int tid = threadIdx.x;
    const int row0 = blockIdx.y * BM;
    const int col0 = blockIdx.x * BN;
    const int ty = tid >> 4;       // 0..15
    const int tx = tid & 15;       // 0..15

    float acc[8][8];
#pragma unroll
    for (int i = 0; i < 8; i++)
#pragma unroll
        for (int j = 0; j < 8; j++) acc[i][j] = 0.f;

    for (int k0 = 0; k0 < K; k0 += BK) {
        // load A tile (128x16) and W tile (128x16), transposed into smem
#pragma unroll
        for (int it = 0; it < 2; it++) {
            int f  = tid + it * 256;     // 0..511 (float4 id)
            int r  = f >> 2;             // 0..127
            int c4 = (f & 3) * 4;        // 0,4,8,12
            float4 va = *(const float4*)&A[(size_t)(row0 + r) * K + k0 + c4];
            As[c4 + 0][r] = va.x; As[c4 + 1][r] = va.y;
            As[c4 + 2][r] = va.z; As[c4 + 3][r] = va.w;
            float4 vw = *(const float4*)&W[(size_t)(col0 + r) * K + k0 + c4];
            Bs[c4 + 0][r] = vw.x; Bs[c4 + 1][r] = vw.y;
            Bs[c4 + 2][r] = vw.z; Bs[c4 + 3][r] = vw.w;
        }
        __syncthreads();

#pragma unroll
        for (int k = 0; k < BK; k++) {
            float a[8], b[8];
            *(float4*)&a[0] = *(float4*)&As[k][ty * 8];
            *(float4*)&a[4] = *(float4*)&As[k][ty * 8 + 4];
            *(float4*)&b[0] = *(float4*)&Bs[k][tx * 8];
            *(float4*)&b[4] = *(float4*)&Bs[k][tx * 8 + 4];
#pragma unroll
            for (int i = 0; i < 8; i++)
#pragma unroll
                for (int j = 0; j < 8; j++)
                    acc[i][j] = fmaf(a[i], b[j], acc[i][j]);
        }
        __syncthreads();
    }

    // epilogue
#pragma unroll
    for (int i = 0; i < 8; i++) {
        int r = row0 + ty * 8 + i;
#pragma unroll
        for (int j4 = 0; j4 < 8; j4 += 4) {
            int c = col0 + tx * 8 + j4;
            float v[4];
#pragma unroll
            for (int j = 0; j < 4; j++) {
                float t = acc[i][j4 + j];
                if (bias) t += bias[c + j];
                if (ACT == 1) t = t / (1.f + __expf(-t));   // silu
                v[j] = t;
            }
            *(float4*)&C[(size_t)r * N + c] = make_float4(v[0], v[1], v[2], v[3]);
        }
    }
}

// ---------------------------------------------------------------------------
// Depthwise conv (KS=3, same-padding along L, per-channel) + dw bias
// in/out: [B, L, C]
// ---------------------------------------------------------------------------
__global__ void dwconv_kernel(const float* __restrict__ in,
                              const float* __restrict__ w,
                              const float* __restrict__ bias,
                              float* __restrict__ out,
                              int L, int C, int total4)
{
    int idx = blockIdx.x * blockDim.x + threadIdx.x;
    if (idx >= total4) return;
    int n4 = C >> 2;
    int c4 = (idx % n4) * 4;
    int l  = (idx / n4) % L;

    float4 cur = ((const float4*)in)[idx];
    const float* cu = (const float*)&cur;
    float r[4];
#pragma unroll
    for (int j = 0; j < 4; j++)
        r[j] = fmaf(cu[j], w[(c4 + j) * 3 + 1], bias[c4 + j]);
    if (l > 0) {
        float4 p = ((const float4*)in)[idx - n4];
        const float* pp = (const float*)&p;
#pragma unroll
        for (int j = 0; j < 4; j++)
            r[j] = fmaf(pp[j], w[(c4 + j) * 3 + 0], r[j]);
    }
    if (l < L - 1) {
        float4 nx = ((const float4*)in)[idx + n4];
        const float* pn = (const float*)&nx;
#pragma unroll
        for (int j = 0; j < 4; j++)
            r[j] = fmaf(pn[j], w[(c4 + j) * 3 + 2], r[j]);
    }
    ((float4*)out)[idx] = make_float4(r[0], r[1], r[2], r[3]);
}

// ---------------------------------------------------------------------------
// L2 norm over contiguous 64-float vectors (one warp per vector), in-place.
// applyTemp: also multiply by 1/temperature[0] (folds score scaling into q).
// ---------------------------------------------------------------------------
__global__ void l2norm_kernel(float* __restrict__ x, const float* __restrict__ tptr,
                              int nvec, int applyTemp)
{
    int vec = blockIdx.x * (blockDim.x >> 5) + (threadIdx.x >> 5);
    if (vec >= nvec) return;
    int lane = threadIdx.x & 31;
    float2* p = (float2*)(x + (size_t)vec * 64);
    float2 v = p[lane];
    float s = fmaf(v.x, v.x, v.y * v.y);
#pragma unroll
    for (int o = 16; o; o >>= 1) s += __shfl_xor_sync(0xffffffffu, s, o);
    float n = fmaxf(sqrtf(s), 1e-12f);
    float inv = 1.0f / n;
    if (applyTemp) inv *= (1.0f / tptr[0]);
    v.x *= inv; v.y *= inv;
    p[lane] = v;
}

// ---------------------------------------------------------------------------
// Polynomial exp for |x| <= ~0.35 (scores bounded by 1/temperature after
// l2norm of q,k). Degree-6 Taylor: rel err < 2e-7 on the needed range.
// ---------------------------------------------------------------------------
__device__ __forceinline__ float exp_small(float x)
{
    float p = 1.f / 720.f;
    p = fmaf(p, x, 1.f / 120.f);
    p = fmaf(p, x, 1.f / 24.f);
    p = fmaf(p, x, 1.f / 6.f);
    p = fmaf(p, x, 0.5f);
    p = fmaf(p, x, 1.f);
    p = fmaf(p, x, 1.f);
    return p;
}

// ---------------------------------------------------------------------------
// Attention: per (b,h), O = softmax(q k^T) v, fused +residual x.
// q already scaled by 1/temperature. No max-subtraction needed (|s|<=0.125
// => exp bounded), so a single streaming pass with running denominator works.
// Tiles: 64 queries x 32 keys, Dh=64. 256 threads.
// Q/K/V layout: [B, L, C] with head h at cols h*64..h*64+63.
// ---------------------------------------------------------------------------
__global__ __launch_bounds__(256)
void attn_kernel(const float* __restrict__ Q, const float* __restrict__ Kd,
                 const float* __restrict__ V, const float* __restrict__ X,
                 float* __restrict__ O, int L, int C, int H)
{
    const int b = blockIdx.y / H;
    const int h = blockIdx.y % H;
    const size_t base = (size_t)b * L * C + (size_t)h * HDIM;
    const float* qb = Q + base;
    const float* kb = Kd + base;
    const float* vb = V + base;
    const int q0 = blockIdx.x * 64;

    __shared__ float sQ[64][64];   // [d][r]  (transposed)
    __shared__ float sK[64][32];   // [d][c]  (transposed)
    __shared__ float sV[32][64];   // [j][d]
    __shared__ float sP[64][32];   // [r][j]
    __shared__ float sDen[64][17];

    const int tid = threadIdx.x;
    const int ty = tid >> 4;       // 0..15
    const int tx = tid & 15;       // 0..15

    // Load Q tile (64 x 64), transpose into sQ[d][r]
#pragma unroll
    for (int it = 0; it < 4; it++) {
        int f  = tid + it * 256;   // 0..1023 (float4 id)
        int r  = f >> 4;           // 0..63
        int d4 = (f & 15) * 4;     // 0..60
        float4 v = *(const float4*)&qb[(size_t)(q0 + r) * C + d4];
        sQ[d4 + 0][r] = v.x; sQ[d4 + 1][r] = v.y;
        sQ[d4 + 2][r] = v.z; sQ[d4 + 3][r] = v.w;
    }
    __syncthreads();

    float Oacc[4][4];
    float denp[4];
#pragma unroll
    for (int i = 0; i < 4; i++) {
        denp[i] = 0.f;
#pragma unroll
        for (int j = 0; j < 4; j++) Oacc[i][j] = 0.f;
    }

    const int nkt = L / 32;
    for (int kt = 0; kt < nkt; kt++) {
        const int k0 = kt * 32;
        // Load K tile (32 keys x 64 d) transposed, V tile direct
#pragma unroll
        for (int it = 0; it < 2; it++) {
            int f  = tid + it * 256;   // 0..511
            int c  = f >> 4;           // 0..31
            int d4 = (f & 15) * 4;
            float4 kv = *(const float4*)&kb[(size_t)(k0 + c) * C + d4];
            sK[d4 + 0][c] = kv.x; sK[d4 + 1][c] = kv.y;
            sK[d4 + 2][c] = kv.z; sK[d4 + 3][c] = kv.w;
            float4 vv = *(const float4*)&vb[(size_t)(k0 + c) * C + d4];
            *(float4*)&sV[c][d4] = vv;
        }
        __syncthreads();

        // S = Q K^T : rows ty*4..+3, cols tx*2..+1
        float s[4][2] = {};
#pragma unroll
        for (int d = 0; d < 64; d++) {
            float a[4];
            *(float4*)a = *(float4*)&sQ[d][ty * 4];
            float2 bk = *(float2*)&sK[d][tx * 2];
#pragma unroll
            for (int i = 0; i < 4; i++) {
                s[i][0] = fmaf(a[i], bk.x, s[i][0]);
                s[i][1] = fmaf(a[i], bk.y, s[i][1]);
            }
        }
        // P = exp(S), partial row sums
#pragma unroll
        for (int i = 0; i < 4; i++)
#pragma unroll
            for (int j = 0; j < 2; j++) {
                float e = exp_small(s[i][j]);
                sP[ty * 4 + i][tx * 2 + j] = e;
                denp[i] += e;
            }
        __syncthreads();

        // O += P V : rows ty*4..+3, cols tx*4..+3
#pragma unroll
        for (int jj = 0; jj < 32; jj++) {
            float a[4];
#pragma unroll
            for (int i = 0; i < 4; i++) a[i] = sP[ty * 4 + i][jj];
            float bv[4];
            *(float4*)bv = *(float4*)&sV[jj][tx * 4];
#pragma unroll
            for (int i = 0; i < 4; i++)
#pragma unroll
                for (int j = 0; j < 4; j++)
                    Oacc[i][j] = fmaf(a[i], bv[j], Oacc[i][j]);
        }
        __syncthreads();
    }

    // Reduce denominator across the 16 tx-threads of each row group
#pragma unroll
    for (int i = 0; i < 4; i++) sDen[ty * 4 + i][tx] = denp[i];
    __syncthreads();
    float den[4];
#pragma unroll
    for (int i = 0; i < 4; i++) {
        float t = 0.f;
#pragma unroll
        for (int u = 0; u < 16; u++) t += sDen[ty * 4 + i][u];
        den[i] = t;
    }

    // Write O/den + residual x
#pragma unroll
    for (int i = 0; i < 4; i++) {
        int r = q0 + ty * 4 + i;
        float inv = 1.f / den[i];
        size_t off = ((size_t)b * L + r) * C + h * HDIM + tx * 4;
        float4 xr = *(const float4*)&X[off];
        float4 o;
        o.x = fmaf(Oacc[i][0], inv, xr.x);
        o.y = fmaf(Oacc[i][1], inv, xr.y);
        o.z = fmaf(Oacc[i][2], inv, xr.z);
        o.w = fmaf(Oacc[i][3], inv, xr.w);
        *(float4*)&O[off] = o;
    }
}

// ---------------------------------------------------------------------------
// LayerNorm over rows of C=1024 (one block of 256 threads per row).
// Optional fused elementwise add of a second tensor before normalization.
// ---------------------------------------------------------------------------
__global__ __launch_bounds__(256)
void layernorm_kernel(const float* __restrict__ in, const float* __restrict__ add,
                      const float* __restrict__ g, const float* __restrict__ bta,
                      float* __restrict__ out, int C)
{
    int row = blockIdx.x;
    int t = threadIdx.x;
    float4 v = ((const float4*)(in + (size_t)row * C))[t];
    if (add) {
        float4 a = ((const float4*)(add + (size_t)row * C))[t];
        v.x += a.x; v.y += a.y; v.z += a.z; v.w += a.w;
    }
    float s  = v.x + v.y + v.z + v.w;
    float s2 = fmaf(v.x, v.x, fmaf(v.y, v.y, fmaf(v.z, v.z, v.w * v.w)));

    __shared__ float red[2][8];
#pragma unroll
    for (int o = 16; o; o >>= 1) {
        s  += __shfl_xor_sync(0xffffffffu, s, o);
        s2 += __shfl_xor_sync(0xffffffffu, s2, o);
    }
    int wid = t >> 5, lane = t & 31;
    if (lane == 0) { red[0][wid] = s; red[1][wid] = s2; }
    __syncthreads();
    if (t < 32) {
        float a  = (lane < 8) ? red[0][lane] : 0.f;
        float b2 = (lane < 8) ? red[1][lane] : 0.f;
#pragma unroll
        for (int o = 4; o; o >>= 1) {
            a  += __shfl_xor_sync(0xffffffffu, a, o);
            b2 += __shfl_xor_sync(0xffffffffu, b2, o);
        }
        if (lane == 0) { red[0][0] = a; red[1][0] = b2; }
    }
    __syncthreads();
    float mean = red[0][0] / C;
    float var  = red[1][0] / C - mean * mean;
    float inv  = rsqrtf(var + 1e-5f);

    float4 gg = ((const float4*)g)[t];
    float4 bb = ((const float4*)bta)[t];
    float4 o;
    o.x = fmaf((v.x - mean) * inv, gg.x, bb.x);
    o.y = fmaf((v.y - mean) * inv, gg.y, bb.y);
    o.z = fmaf((v.z - mean) * inv, gg.z, bb.z);
    o.w = fmaf((v.w - mean) * inv, gg.w, bb.w);
    ((float4*)(out + (size_t)row * C))[t] = o;
}

// ---------------------------------------------------------------------------
// gated = gp[:, :C] * silu(gp[:, C:])
// ---------------------------------------------------------------------------
__global__ void gated_kernel(const float* __restrict__ gp, float* __restrict__ out,
                             int M, int C)
{
    int idx = blockIdx.x * blockDim.x + threadIdx.x;
    int n4 = C >> 2;
    if (idx >= M * n4) return;
    int m = idx / n4, c4 = idx % n4;
    const float4* rowp = (const float4*)(gp + (size_t)m * 2 * C);
    float4 val = rowp[c4];
    float4 gt  = rowp[n4 + c4];
    float4 o;
    o.x = val.x * (gt.x / (1.f + __expf(-gt.x)));
    o.y = val.y * (gt.y / (1.f + __expf(-gt.y)));
    o.z = val.z * (gt.z / (1.f + __expf(-gt.z)));
    o.w = val.w * (gt.w / (1.f + __expf(-gt.w)));
    ((float4*)out)[idx] = o;
}

// ---------------------------------------------------------------------------
// Launch
// ---------------------------------------------------------------------------
extern "C" void kernel_launch(void* const* d_in, const int* in_sizes, int n_in,
                              void* d_out, int out_size)
{
    const float* x       = (const float*)d_in[0];
    const float* wq      = (const float*)d_in[1];
    const float* wk      = (const float*)d_in[2];
    const float* wv      = (const float*)d_in[3];
    const float* q_dw_w  = (const float*)d_in[4];
    const float* q_dw_b  = (const float*)d_in[5];
    const float* q_pw_w  = (const float*)d_in[6];
    const float* q_pw_b  = (const float*)d_in[7];
    const float* k_dw_w  = (const float*)d_in[8];
    const float* k_dw_b  = (const float*)d_in[9];
    const float* k_pw_w  = (const float*)d_in[10];
    const float* k_pw_b  = (const float*)d_in[11];
    const float* v_dw_w  = (const float*)d_in[12];
    const float* v_dw_b  = (const float*)d_in[13];
    const float* v_pw_w  = (const float*)d_in[14];
    const float* v_pw_b  = (const float*)d_in[15];
    const float* gn_g    = (const float*)d_in[16];
    const float* gn_b    = (const float*)d_in[17];
    const float* w_gate  = (const float*)d_in[18];
    const float* w_out   = (const float*)d_in[19];
    const float* b_out   = (const float*)d_in[20];
    const float* temp    = (const float*)d_in[21];
    const float* fn_g    = (const float*)d_in[22];
    const float* fn_b    = (const float*)d_in[23];
    float* out = (float*)d_out;

    const int C = DIM;
    const int L = SEQ;
    const int M = in_sizes[0] / C;     // B*L = 4096
    const int B = M / L;               // 2
    const int H = NHEADS;

    float *q1, *k1, *v1, *tmp, *attn, *nrm, *gp;
    cudaGetSymbolAddress((void**)&q1,  g_q1);
    cudaGetSymbolAddress((void**)&k1,  g_k1);
    cudaGetSymbolAddress((void**)&v1,  g_v1);
    cudaGetSymbolAddress((void**)&tmp, g_tmp);
    cudaGetSymbolAddress((void**)&attn,g_attn);
    cudaGetSymbolAddress((void**)&nrm, g_norm);
    cudaGetSymbolAddress((void**)&gp,  g_gp);

    dim3 gThr(256);
    dim3 g1(C / 128, M / 128);           // 8 x 32
    dim3 g2(2 * C / 128, M / 128);       // 16 x 32

    // q/k/v projections + silu
    gemm128<1><<<g1, gThr>>>(x, wq, nullptr, q1, M, C, C);
    gemm128<1><<<g1, gThr>>>(x, wk, nullptr, k1, M, C, C);
    gemm128<1><<<g1, gThr>>>(x, wv, nullptr, v1, M, C, C);

    const int total4 = M * C / 4;
    const int dwBlocks = (total4 + 255) / 256;

    // dsconv: depthwise (+dw bias) then pointwise GEMM (+pw bias)
    dwconv_kernel<<<dwBlocks, 256>>>(q1, q_dw_w, q_dw_b, tmp, L, C, total4);
    gemm128<0><<<g1, gThr>>>(tmp, q_pw_w, q_pw_b, q1, M, C, C);
    dwconv_kernel<<<dwBlocks, 256>>>(k1, k_dw_w, k_dw_b, tmp, L, C, total4);
    gemm128<0><<<g1, gThr>>>(tmp, k_pw_w, k_pw_b, k1, M, C, C);
    dwconv_kernel<<<dwBlocks, 256>>>(v1, v_dw_w, v_dw_b, tmp, L, C, total4);
    gemm128<0><<<g1, gThr>>>(tmp, v_pw_w, v_pw_b, v1, M, C, C);

    // l2norm q (with 1/temperature folded in) and k; v untouched
    const int nvec = M * H;                       // 65536
    const int lnBlocks = nvec / 8;
    l2norm_kernel<<<lnBlocks, 256>>>(q1, temp, nvec, 1);
    l2norm_kernel<<<lnBlocks, 256>>>(k1, temp, nvec, 0);

    // attention + residual
    dim3 ga(L / 64, B * H);
    attn_kernel<<<ga, gThr>>>(q1, k1, v1, x, attn, L, C, H);

    // group norm (plain layernorm over C)
    layernorm_kernel<<<M, 256>>>(attn, nullptr, gn_g, gn_b, nrm, C);

    // gate projection, gating, output projection
    gemm128<0><<<g2, gThr>>>(nrm, w_gate, nullptr, gp, M, 2 * C, C);
    gated_kernel<<<(M * C / 4 + 255) / 256, 256>>>(gp, tmp, M, C);
    gemm128<0><<<g1, gThr>>>(tmp, w_out, b_out, q1, M, C, C);

    // final layernorm with fused residual (out + attn_out)
    layernorm_kernel<<<M, 256>>>(q1, attn, fn_g, fn_b, out, C);
}

// round 4
// speedup vs baseline: 2.6628x; 2.6628x over previous
#include <cuda_runtime.h>
#include <cuda_bf16.h>
#include <cstdint>

#define DIM 1024
#define SEQ 2048
#define NHEADS 16
#define HDIM 64

// ---------------------------------------------------------------------------
// Static scratch (allocation-free contract: __device__ globals)
// ---------------------------------------------------------------------------
#define MMAX (2 * SEQ)           // B*L = 4096
__device__ float g_q1[MMAX * DIM];
__device__ float g_k1[MMAX * DIM];
__device__ float g_v1[MMAX * DIM];
__device__ float g_tmp[MMAX * DIM];
__device__ float g_attn[MMAX * DIM];
__device__ float g_norm[MMAX * DIM];
__device__ float g_gp[MMAX * 2 * DIM];

// ---------------------------------------------------------------------------
// tf32 helpers
// ---------------------------------------------------------------------------
__device__ __forceinline__ float to_tf32(float x) {
    uint32_t u;
    asm("cvt.rna.tf32.f32 %0, %1;" : "=r"(u) : "f"(x));
    return __uint_as_float(u);
}

__device__ __forceinline__ void mma_tf32(float* d, const uint32_t* a, const uint32_t* b) {
    asm volatile(
        "mma.sync.aligned.m16n8k8.row.col.f32.tf32.tf32.f32 "
        "{%0,%1,%2,%3}, {%4,%5,%6,%7}, {%8,%9}, {%0,%1,%2,%3};"
        : "+f"(d[0]), "+f"(d[1]), "+f"(d[2]), "+f"(d[3])
        : "r"(a[0]), "r"(a[1]), "r"(a[2]), "r"(a[3]), "r"(b[0]), "r"(b[1]));
}

// ===========================================================================
// tf32 mma.sync GEMM:  C[m,n] = act( sum_k A[m,k]*W[n,k] + bias[n] )
// A: MxK row-major, W: NxK row-major. Block tile 256x128, BK=16, 256 threads,
// 8 warps as 4(m) x 2(n), warp tile 64x64. Double-buffered smem.
// Smem rows padded to 20 floats -> all fragment LDS conflict-free.
// ACT: 0=none, 1=silu
// ===========================================================================
#define GPK 20
#define GEMM_SMEM_FLOATS (2 * 256 * GPK + 2 * 128 * GPK + 128)
#define GEMM_SMEM_BYTES  (GEMM_SMEM_FLOATS * 4)

template<int ACT>
__global__ __launch_bounds__(256)
void gemm_mma(const float* __restrict__ A, const float* __restrict__ W,
              const float* __restrict__ bias, float* __restrict__ C,
              int M, int N, int K)
{
    extern __shared__ float sm[];
    float* As = sm;                        // [2][256][GPK]
    float* Bs = sm + 2 * 256 * GPK;        // [2][128][GPK]
    float* sb = sm + 2 * 256 * GPK + 2 * 128 * GPK;   // [128]

    const int tid = threadIdx.x;
    const int wid = tid >> 5, lane = tid & 31;
    const int g = lane >> 2, tg = lane & 3;
    const int wm = wid >> 1, wn = wid & 1;
    const int row0 = blockIdx.y * 256, col0 = blockIdx.x * 128;

    if (tid < 128) sb[tid] = bias ? bias[col0 + tid] : 0.f;

    float acc[4][8][4];
#pragma unroll
    for (int a0 = 0; a0 < 4; a0++)
#pragma unroll
        for (int b0 = 0; b0 < 8; b0++)
#pragma unroll
            for (int c0 = 0; c0 < 4; c0++) acc[a0][b0][c0] = 0.f;

    float4 ra[4], rb[2];
    const int NC = K / 16;

    // prologue: load chunk 0
#pragma unroll
    for (int it = 0; it < 4; it++) {
        int f = tid + it * 256, r = f >> 2, c4 = (f & 3) * 4;
        ra[it] = *(const float4*)&A[(size_t)(row0 + r) * K + c4];
    }
#pragma unroll
    for (int it = 0; it < 2; it++) {
        int f = tid + it * 256, r = f >> 2, c4 = (f & 3) * 4;
        rb[it] = *(const float4*)&W[(size_t)(col0 + r) * K + c4];
    }
#pragma unroll
    for (int it = 0; it < 4; it++) {
        int f = tid + it * 256, r = f >> 2, c4 = (f & 3) * 4;
        float* p = As + r * GPK + c4;
        p[0] = to_tf32(ra[it].x); p[1] = to_tf32(ra[it].y);
        p[2] = to_tf32(ra[it].z); p[3] = to_tf32(ra[it].w);
    }
#pragma unroll
    for (int it = 0; it < 2; it++) {
        int f = tid + it * 256, r = f >> 2, c4 = (f & 3) * 4;
        float* p = Bs + r * GPK + c4;
        p[0] = to_tf32(rb[it].x); p[1] = to_tf32(rb[it].y);
        p[2] = to_tf32(rb[it].z); p[3] = to_tf32(rb[it].w);
    }
    __syncthreads();

    for (int i = 0; i < NC; i++) {
        const int cur = i & 1;
        if (i + 1 < NC) {
#pragma unroll
            for (int it = 0; it < 4; it++) {
                int f = tid + it * 256, r = f >> 2, c4 = (f & 3) * 4;
                ra[it] = *(const float4*)&A[(size_t)(row0 + r) * K + (i + 1) * 16 + c4];
            }
#pragma unroll
            for (int it = 0; it < 2; it++) {
                int f = tid + it * 256, r = f >> 2, c4 = (f & 3) * 4;
                rb[it] = *(const float4*)&W[(size_t)(col0 + r) * K + (i + 1) * 16 + c4];
            }
        }

        const uint32_t* Au = (const uint32_t*)(As + cur * 256 * GPK);
        const uint32_t* Bu = (const uint32_t*)(Bs + cur * 128 * GPK);
#pragma unroll
        for (int ks = 0; ks < 2; ks++) {
            uint32_t af[4][4], bf[8][2];
#pragma unroll
            for (int mt = 0; mt < 4; mt++) {
                int m = wm * 64 + mt * 16;
                af[mt][0] = Au[(m + g)     * GPK + ks * 8 + tg];
                af[mt][1] = Au[(m + g + 8) * GPK + ks * 8 + tg];
                af[mt][2] = Au[(m + g)     * GPK + ks * 8 + tg + 4];
                af[mt][3] = Au[(m + g + 8) * GPK + ks * 8 + tg + 4];
            }
#pragma unroll
            for (int nt = 0; nt < 8; nt++) {
                int n = wn * 64 + nt * 8;
                bf[nt][0] = Bu[(n + g) * GPK + ks * 8 + tg];
                bf[nt][1] = Bu[(n + g) * GPK + ks * 8 + tg + 4];
            }
#pragma unroll
            for (int mt = 0; mt < 4; mt++)
#pragma unroll
                for (int nt = 0; nt < 8; nt++)
                    mma_tf32(acc[mt][nt], af[mt], bf[nt]);
        }

        if (i + 1 < NC) {
            const int nxt = (i + 1) & 1;
#pragma unroll
            for (int it = 0; it < 4; it++) {
                int f = tid + it * 256, r = f >> 2, c4 = (f & 3) * 4;
                float* p = As + nxt * 256 * GPK + r * GPK + c4;
                p[0] = to_tf32(ra[it].x); p[1] = to_tf32(ra[it].y);
                p[2] = to_tf32(ra[it].z); p[3] = to_tf32(ra[it].w);
            }
#pragma unroll
            for (int it = 0; it < 2; it++) {
                int f = tid + it * 256, r = f >> 2, c4 = (f & 3) * 4;
                float* p = Bs + nxt * 128 * GPK + r * GPK + c4;
                p[0] = to_tf32(rb[it].x); p[1] = to_tf32(rb[it].y);
                p[2] = to_tf32(rb[it].z); p[3] = to_tf32(rb[it].w);
            }
        }
        __syncthreads();
    }

    // epilogue: bias + optional silu, float2 stores
#pragma unroll
    for (int mt = 0; mt < 4; mt++) {
        int r_ = row0 + wm * 64 + mt * 16 + g;
#pragma unroll
        for (int nt = 0; nt < 8; nt++) {
            int cl = wn * 64 + nt * 8 + tg * 2;
            float b0 = sb[cl], b1 = sb[cl + 1];
            float v0 = acc[mt][nt][0] + b0, v1 = acc[mt][nt][1] + b1;
            float v2 = acc[mt][nt][2] + b0, v3 = acc[mt][nt][3] + b1;
            if (ACT == 1) {
                v0 = v0 / (1.f + __expf(-v0)); v1 = v1 / (1.f + __expf(-v1));
                v2 = v2 / (1.f + __expf(-v2)); v3 = v3 / (1.f + __expf(-v3));
            }
            *(float2*)&C[(size_t)r_ * N + col0 + cl] = make_float2(v0, v1);
            *(float2*)&C[(size_t)(r_ + 8) * N + col0 + cl] = make_float2(v2, v3);
        }
    }
}

// ---------------------------------------------------------------------------
// Depthwise conv (KS=3, same-padding along L, per-channel) + dw bias
// ---------------------------------------------------------------------------
__global__ void dwconv_kernel(const float* __restrict__ in,
                              const float* __restrict__ w,
                              const float* __restrict__ bias,
                              float* __restrict__ out,
                              int L, int C, int total4)
{
    int idx = blockIdx.x * blockDim.x + threadIdx.x;
    if (idx >= total4) return;
    int n4 = C >> 2;
    int c4 = (idx % n4) * 4;
    int l  = (idx / n4) % L;

    float4 cur = ((const float4*)in)[idx];
    const float* cu = (const float*)&cur;
    float r[4];
#pragma unroll
    for (int j = 0; j < 4; j++)
        r[j] = fmaf(cu[j], w[(c4 + j) * 3 + 1], bias[c4 + j]);
    if (l > 0) {
        float4 p = ((const float4*)in)[idx - n4];
        const float* pp = (const float*)&p;
#pragma unroll
        for (int j = 0; j < 4; j++)
            r[j] = fmaf(pp[j], w[(c4 + j) * 3 + 0], r[j]);
    }
    if (l < L - 1) {
        float4 nx = ((const float4*)in)[idx + n4];
        const float* pn = (const float*)&nx;
#pragma unroll
        for (int j = 0; j < 4; j++)
            r[j] = fmaf(pn[j], w[(c4 + j) * 3 + 2], r[j]);
    }
    ((float4*)out)[idx] = make_float4(r[0], r[1], r[2], r[3]);
}

// ---------------------------------------------------------------------------
// L2 norm over contiguous 64-float vectors (one warp per vector), in-place.
// ---------------------------------------------------------------------------
__global__ void l2norm_kernel(float* __restrict__ x, const float* __restrict__ tptr,
                              int nvec, int applyTemp)
{
    int vec = blockIdx.x * (blockDim.x >> 5) + (threadIdx.x >> 5);
    if (vec >= nvec) return;
    int lane = threadIdx.x & 31;
    float2* p = (float2*)(x + (size_t)vec * 64);
    float2 v = p[lane];
    float s = fmaf(v.x, v.x, v.y * v.y);
#pragma unroll
    for (int o = 16; o; o >>= 1) s += __shfl_xor_sync(0xffffffffu, s, o);
    float n = fmaxf(sqrtf(s), 1e-12f);
    float inv = 1.0f / n;
    if (applyTemp) inv *= (1.0f / tptr[0]);
    v.x *= inv; v.y *= inv;
    p[lane] = v;
}

// ---------------------------------------------------------------------------
// Polynomial exp for |x| <= ~0.35 (scores bounded after l2norm + /temp)
// ---------------------------------------------------------------------------
__device__ __forceinline__ float exp_small(float x)
{
    float p = 1.f / 720.f;
    p = fmaf(p, x, 1.f / 120.f);
    p = fmaf(p, x, 1.f / 24.f);
    p = fmaf(p, x, 1.f / 6.f);
    p = fmaf(p, x, 0.5f);
    p = fmaf(p, x, 1.f);
    p = fmaf(p, x, 1.f);
    return p;
}

// ===========================================================================
// Attention via tf32 mma.sync: per (b,h), O = softmax(q k^T) v, fused +x.
// 64 queries/block, 32-key tiles, Dh=64. 128 threads = 4 warps, each warp
// owns 16 query rows (m16). S and PV both m16n8k8 tf32 mma.
// Pad strides chosen for conflict-free fragment LDS:
//   A-type (row index = groupID): stride % 32 == 4  -> sQ 68, sP 36, sK 68
//   B-type (row index = tig):     stride % 32 == 8  -> sV 72
// ===========================================================================
__global__ __launch_bounds__(128)
void attn_mma(const float* __restrict__ Q, const float* __restrict__ Kd,
              const float* __restrict__ V, const float* __restrict__ X,
              float* __restrict__ O, int L, int C, int H)
{
    const int b = blockIdx.y / H;
    const int h = blockIdx.y % H;
    const size_t base = (size_t)b * L * C + (size_t)h * HDIM;
    const int q0 = blockIdx.x * 64;

    __shared__ float sQ[64][68];
    __shared__ float sK[32][68];
    __shared__ float sV[32][72];
    __shared__ float sP[64][36];

    const int tid = threadIdx.x;
    const int wid = tid >> 5, lane = tid & 31;
    const int g = lane >> 2, tg = lane & 3;
    const int qw = wid * 16;

    // Load Q tile (64x64), tf32-rounded
#pragma unroll
    for (int it = 0; it < 8; it++) {
        int f = tid + it * 128, q = f >> 4, d4 = (f & 15) * 4;
        float4 v = *(const float4*)&Q[base + (size_t)(q0 + q) * C + d4];
        sQ[q][d4 + 0] = to_tf32(v.x); sQ[q][d4 + 1] = to_tf32(v.y);
        sQ[q][d4 + 2] = to_tf32(v.z); sQ[q][d4 + 3] = to_tf32(v.w);
    }

    float Oacc[8][4];
#pragma unroll
    for (int i = 0; i < 8; i++)
#pragma unroll
        for (int j = 0; j < 4; j++) Oacc[i][j] = 0.f;
    float den0 = 0.f, den1 = 0.f;

    const int nkt = L / 32;
    for (int kt = 0; kt < nkt; kt++) {
        const int k0 = kt * 32;
        __syncthreads();   // protect prior sK/sV reads (also orders Q on kt=0)
#pragma unroll
        for (int it = 0; it < 4; it++) {
            int f = tid + it * 128, j = f >> 4, d4 = (f & 15) * 4;
            float4 kv = *(const float4*)&Kd[base + (size_t)(k0 + j) * C + d4];
            sK[j][d4 + 0] = to_tf32(kv.x); sK[j][d4 + 1] = to_tf32(kv.y);
            sK[j][d4 + 2] = to_tf32(kv.z); sK[j][d4 + 3] = to_tf32(kv.w);
            float4 vv = *(const float4*)&V[base + (size_t)(k0 + j) * C + d4];
            sV[j][d4 + 0] = to_tf32(vv.x); sV[j][d4 + 1] = to_tf32(vv.y);
            sV[j][d4 + 2] = to_tf32(vv.z); sV[j][d4 + 3] = to_tf32(vv.w);
        }
        __syncthreads();

        // ---- S = Q K^T  (m16 x n32, k=64) ----
        float sAcc[4][4];
#pragma unroll
        for (int nt = 0; nt < 4; nt++)
#pragma unroll
            for (int j = 0; j < 4; j++) sAcc[nt][j] = 0.f;

#pragma unroll
        for (int ks = 0; ks < 8; ks++) {
            uint32_t a[4];
            a[0] = __float_as_uint(sQ[qw + g]    [ks * 8 + tg]);
            a[1] = __float_as_uint(sQ[qw + g + 8][ks * 8 + tg]);
            a[2] = __float_as_uint(sQ[qw + g]    [ks * 8 + tg + 4]);
            a[3] = __float_as_uint(sQ[qw + g + 8][ks * 8 + tg + 4]);
#pragma unroll
            for (int nt = 0; nt < 4; nt++) {
                uint32_t bb[2];
                bb[0] = __float_as_uint(sK[nt * 8 + g][ks * 8 + tg]);
                bb[1] = __float_as_uint(sK[nt * 8 + g][ks * 8 + tg + 4]);
                mma_tf32(sAcc[nt], a, bb);
            }
        }

        // ---- P = exp(S), row-sum partials, store tf32 P ----
#pragma unroll
        for (int nt = 0; nt < 4; nt++) {
            float p0 = exp_small(sAcc[nt][0]);
            float p1 = exp_small(sAcc[nt][1]);
            float p2 = exp_small(sAcc[nt][2]);
            float p3 = exp_small(sAcc[nt][3]);
            den0 += p0 + p1;
            den1 += p2 + p3;
            sP[qw + g]    [nt * 8 + tg * 2]     = to_tf32(p0);
            sP[qw + g]    [nt * 8 + tg * 2 + 1] = to_tf32(p1);
            sP[qw + g + 8][nt * 8 + tg * 2]     = to_tf32(p2);
            sP[qw + g + 8][nt * 8 + tg * 2 + 1] = to_tf32(p3);
        }
        __syncwarp();   // sP rows are warp-private

        // ---- O += P V  (m16 x n64, k=32) ----
#pragma unroll
        for (int ks = 0; ks < 4; ks++) {
            uint32_t a[4];
            a[0] = __float_as_uint(sP[qw + g]    [ks * 8 + tg]);
            a[1] = __float_as_uint(sP[qw + g + 8][ks * 8 + tg]);
            a[2] = __float_as_uint(sP[qw + g]    [ks * 8 + tg + 4]);
            a[3] = __float_as_uint(sP[qw + g + 8][ks * 8 + tg + 4]);
#pragma unroll
            for (int nt = 0; nt < 8; nt++) {
                uint32_t bb[2];
                bb[0] = __float_as_uint(sV[ks * 8 + tg]    [nt * 8 + g]);
                bb[1] = __float_as_uint(sV[ks * 8 + tg + 4][nt * 8 + g]);
                mma_tf32(Oacc[nt], a, bb);
            }
        }
        __syncwarp();
    }

    // denominator: reduce across the 4 lanes sharing a groupID
    den0 += __shfl_xor_sync(0xffffffffu, den0, 1);
    den0 += __shfl_xor_sync(0xffffffffu, den0, 2);
    den1 += __shfl_xor_sync(0xffffffffu, den1, 1);
    den1 += __shfl_xor_sync(0xffffffffu, den1, 2);
    const float inv0 = 1.f / den0;
    const float inv1 = 1.f / den1;

    // epilogue: O/den + residual X
#pragma unroll
    for (int nt = 0; nt < 8; nt++) {
        int col = h * HDIM + nt * 8 + tg * 2;
        int r0_ = q0 + qw + g;
        size_t off0 = ((size_t)b * L + r0_) * C + col;
        size_t off1 = ((size_t)b * L + r0_ + 8) * C + col;
        float2 x0 = *(const float2*)&X[off0];
        float2 x1 = *(const float2*)&X[off1];
        float2 o0 = make_float2(fmaf(Oacc[nt][0], inv0, x0.x),
                                fmaf(Oacc[nt][1], inv0, x0.y));
        float2 o1 = make_float2(fmaf(Oacc[nt][2], inv1, x1.x),
                                fmaf(Oacc[nt][3], inv1, x1.y));
        *(float2*)&O[off0] = o0;
        *(float2*)&O[off1] = o1;
    }
}

// ---------------------------------------------------------------------------
// LayerNorm over rows of C=1024 (one block of 256 threads per row).
// ---------------------------------------------------------------------------
__global__ __launch_bounds__(256)
void layernorm_kernel(const float* __restrict__ in, const float* __restrict__ add,
                      const float* __restrict__ g, const float* __restrict__ bta,
                      float* __restrict__ out, int C)
{
    int row = blockIdx.x;
    int t = threadIdx.x;
    float4 v = ((const float4*)(in + (size_t)row * C))[t];
    if (add) {
        float4 a = ((const float4*)(add + (size_t)row * C))[t];
        v.x += a.x; v.y += a.y; v.z += a.z; v.w += a.w;
    }
    float s  = v.x + v.y + v.z + v.w;
    float s2 = fmaf(v.x, v.x, fmaf(v.y, v.y, fmaf(v.z, v.z, v.w * v.w)));

    __shared__ float red[2][8];
#pragma unroll
    for (int o = 16; o; o >>= 1) {
        s  += __shfl_xor_sync(0xffffffffu, s, o);
        s2 += __shfl_xor_sync(0xffffffffu, s2, o);
    }
    int wid = t >> 5, lane = t & 31;
    if (lane == 0) { red[0][wid] = s; red[1][wid] = s2; }
    __syncthreads();
    if (t < 32) {
        float a  = (lane < 8) ? red[0][lane] : 0.f;
        float b2 = (lane < 8) ? red[1][lane] : 0.f;
#pragma unroll
        for (int o = 4; o; o >>= 1) {
            a  += __shfl_xor_sync(0xffffffffu, a, o);
            b2 += __shfl_xor_sync(0xffffffffu, b2, o);
        }
        if (lane == 0) { red[0][0] = a; red[1][0] = b2; }
    }
    __syncthreads();
    float mean = red[0][0] / C;
    float var  = red[1][0] / C - mean * mean;
    float inv  = rsqrtf(var + 1e-5f);

    float4 gg = ((const float4*)g)[t];
    float4 bb = ((const float4*)bta)[t];
    float4 o;
    o.x = fmaf((v.x - mean) * inv, gg.x, bb.x);
    o.y = fmaf((v.y - mean) * inv, gg.y, bb.y);
    o.z = fmaf((v.z - mean) * inv, gg.z, bb.z);
    o.w = fmaf((v.w - mean) * inv, gg.w, bb.w);
    ((float4*)(out + (size_t)row * C))[t] = o;
}

// ---------------------------------------------------------------------------
// gated = gp[:, :C] * silu(gp[:, C:])
// ---------------------------------------------------------------------------
__global__ void gated_kernel(const float* __restrict__ gp, float* __restrict__ out,
                             int M, int C)
{
    int idx = blockIdx.x * blockDim.x + threadIdx.x;
    int n4 = C >> 2;
    if (idx >= M * n4) return;
    int m = idx / n4, c4 = idx % n4;
    const float4* rowp = (const float4*)(gp + (size_t)m * 2 * C);
    float4 val = rowp[c4];
    float4 gt  = rowp[n4 + c4];
    float4 o;
    o.x = val.x * (gt.x / (1.f + __expf(-gt.x)));
    o.y = val.y * (gt.y / (1.f + __expf(-gt.y)));
    o.z = val.z * (gt.z / (1.f + __expf(-gt.z)));
    o.w = val.w * (gt.w / (1.f + __expf(-gt.w)));
    ((float4*)out)[idx] = o;
}

// ---------------------------------------------------------------------------
// Launch
// ---------------------------------------------------------------------------
extern "C" void kernel_launch(void* const* d_in, const int* in_sizes, int n_in,
                              void* d_out, int out_size)
{
    const float* x       = (const float*)d_in[0];
    const float* wq      = (const float*)d_in[1];
    const float* wk      = (const float*)d_in[2];
    const float* wv      = (const float*)d_in[3];
    const float* q_dw_w  = (const float*)d_in[4];
    const float* q_dw_b  = (const float*)d_in[5];
    const float* q_pw_w  = (const float*)d_in[6];
    const float* q_pw_b  = (const float*)d_in[7];
    const float* k_dw_w  = (const float*)d_in[8];
    const float* k_dw_b  = (const float*)d_in[9];
    const float* k_pw_w  = (const float*)d_in[10];
    const float* k_pw_b  = (const float*)d_in[11];
    const float* v_dw_w  = (const float*)d_in[12];
    const float* v_dw_b  = (const float*)d_in[13];
    const float* v_pw_w  = (const float*)d_in[14];
    const float* v_pw_b  = (const float*)d_in[15];
    const float* gn_g    = (const float*)d_in[16];
    const float* gn_b    = (const float*)d_in[17];
    const float* w_gate  = (const float*)d_in[18];
    const float* w_out   = (const float*)d_in[19];
    const float* b_out   = (const float*)d_in[20];
    const float* temp    = (const float*)d_in[21];
    const float* fn_g    = (const float*)d_in[22];
    const float* fn_b    = (const float*)d_in[23];
    float* out = (float*)d_out;

    const int C = DIM;
    const int L = SEQ;
    const int M = in_sizes[0] / C;     // B*L = 4096
    const int B = M / L;               // 2
    const int H = NHEADS;

    float *q1, *k1, *v1, *tmp, *attn, *nrm, *gp;
    cudaGetSymbolAddress((void**)&q1,  g_q1);
    cudaGetSymbolAddress((void**)&k1,  g_k1);
    cudaGetSymbolAddress((void**)&v1,  g_v1);
    cudaGetSymbolAddress((void**)&tmp, g_tmp);
    cudaGetSymbolAddress((void**)&attn,g_attn);
    cudaGetSymbolAddress((void**)&nrm, g_norm);
    cudaGetSymbolAddress((void**)&gp,  g_gp);

    cudaFuncSetAttribute((const void*)gemm_mma<0>,
                         cudaFuncAttributeMaxDynamicSharedMemorySize, GEMM_SMEM_BYTES);
    cudaFuncSetAttribute((const void*)gemm_mma<1>,
                         cudaFuncAttributeMaxDynamicSharedMemorySize, GEMM_SMEM_BYTES);

    dim3 gThr(256);
    dim3 g1(C / 128, M / 256);            // 8 x 16
    dim3 g2(2 * C / 128, M / 256);        // 16 x 16

    // q/k/v projections + silu (tf32 mma)
    gemm_mma<1><<<g1, gThr, GEMM_SMEM_BYTES>>>(x, wq, nullptr, q1, M, C, C);
    gemm_mma<1><<<g1, gThr, GEMM_SMEM_BYTES>>>(x, wk, nullptr, k1, M, C, C);
    gemm_mma<1><<<g1, gThr, GEMM_SMEM_BYTES>>>(x, wv, nullptr, v1, M, C, C);

    const int total4 = M * C / 4;
    const int dwBlocks = (total4 + 255) / 256;

    // dsconv: depthwise (+dw bias) then pointwise GEMM (+pw bias)
    dwconv_kernel<<<dwBlocks, 256>>>(q1, q_dw_w, q_dw_b, tmp, L, C, total4);
    gemm_mma<0><<<g1, gThr, GEMM_SMEM_BYTES>>>(tmp, q_pw_w, q_pw_b, q1, M, C, C);
    dwconv_kernel<<<dwBlocks, 256>>>(k1, k_dw_w, k_dw_b, tmp, L, C, total4);
    gemm_mma<0><<<g1, gThr, GEMM_SMEM_BYTES>>>(tmp, k_pw_w, k_pw_b, k1, M, C, C);
    dwconv_kernel<<<dwBlocks, 256>>>(v1, v_dw_w, v_dw_b, tmp, L, C, total4);
    gemm_mma<0><<<g1, gThr, GEMM_SMEM_BYTES>>>(tmp, v_pw_w, v_pw_b, v1, M, C, C);

    // l2norm q (with 1/temperature folded in) and k
    const int nvec = M * H;                       // 65536
    const int lnBlocks = nvec / 8;
    l2norm_kernel<<<lnBlocks, 256>>>(q1, temp, nvec, 1);
    l2norm_kernel<<<lnBlocks, 256>>>(k1, temp, nvec, 0);

    // attention + residual (tf32 mma)
    dim3 ga(L / 64, B * H);
    attn_mma<<<ga, 128>>>(q1, k1, v1, x, attn, L, C, H);

    // group norm
    layernorm_kernel<<<M, 256>>>(attn, nullptr, gn_g, gn_b, nrm, C);

    // gate projection, gating, output projection
    gemm_mma<0><<<g2, gThr, GEMM_SMEM_BYTES>>>(nrm, w_gate, nullptr, gp, M, 2 * C, C);
    gated_kernel<<<(M * C / 4 + 255) / 256, 256>>>(gp, tmp, M, C);
    gemm_mma<0><<<g1, gThr, GEMM_SMEM_BYTES>>>(tmp, w_out, b_out, q1, M, C, C);

    // final layernorm with fused residual (out + attn_out)
    layernorm_kernel<<<M, 256>>>(q1, attn, fn_g, fn_b, out, C);
}

// round 5
// speedup vs baseline: 4.5828x; 1.7210x over previous
#include <cuda_runtime.h>
#include <cuda_bf16.h>
#include <cstdint>

#define DIM 1024
#define SEQ 2048
#define NHEADS 16
#define HDIM 64
#define MMAX (2 * SEQ)           // B*L = 4096

typedef __nv_bfloat16 bf16;
typedef __nv_bfloat162 bf162;

// ---------------------------------------------------------------------------
// Static scratch (allocation-free contract: __device__ globals)
// ---------------------------------------------------------------------------
__device__ bf16 b_x[MMAX * DIM];
__device__ bf16 b_wq[DIM * DIM];
__device__ bf16 b_wk[DIM * DIM];
__device__ bf16 b_wv[DIM * DIM];
__device__ bf16 b_qpw[DIM * DIM];
__device__ bf16 b_kpw[DIM * DIM];
__device__ bf16 b_vpw[DIM * DIM];
__device__ bf16 b_wg[2 * DIM * DIM];
__device__ bf16 b_wo[DIM * DIM];
__device__ bf16 b_t1[MMAX * DIM];
__device__ bf16 b_t2[MMAX * DIM];
__device__ bf16 b_q[MMAX * DIM];
__device__ bf16 b_k[MMAX * DIM];
__device__ bf16 b_v[MMAX * DIM];
__device__ bf16 b_nrm[MMAX * DIM];
__device__ bf16 b_gp[MMAX * 2 * DIM];
__device__ bf16 b_gated[MMAX * DIM];
__device__ float g_attn[MMAX * DIM];
__device__ float g_o[MMAX * DIM];

// ---------------------------------------------------------------------------
// helpers
// ---------------------------------------------------------------------------
__device__ __forceinline__ uint32_t smem_u32(const void* p) {
    uint32_t a;
    asm("{ .reg .u64 t; cvta.to.shared.u64 t, %1; cvt.u32.u64 %0, t; }"
        : "=r"(a) : "l"(p));
    return a;
}
#define CP16(dst, src) \
    asm volatile("cp.async.cg.shared.global [%0], [%1], 16;" :: "r"(dst), "l"(src))
#define CP_COMMIT() asm volatile("cp.async.commit_group;" ::: "memory")
#define CP_WAIT1()  asm volatile("cp.async.wait_group 1;" ::: "memory")

__device__ __forceinline__ void mma_bf(float* d, const uint32_t* a, const uint32_t* b) {
    asm volatile(
        "mma.sync.aligned.m16n8k16.row.col.f32.bf16.bf16.f32 "
        "{%0,%1,%2,%3}, {%4,%5,%6,%7}, {%8,%9}, {%0,%1,%2,%3};"
        : "+f"(d[0]), "+f"(d[1]), "+f"(d[2]), "+f"(d[3])
        : "r"(a[0]), "r"(a[1]), "r"(a[2]), "r"(a[3]), "r"(b[0]), "r"(b[1]));
}
__device__ __forceinline__ uint32_t packbf(float lo, float hi) {
    bf162 h = __floats2bfloat162_rn(lo, hi);
    return *(uint32_t*)&h;
}

// ---------------------------------------------------------------------------
// fp32 -> bf16 convert (n4 = element count / 4)
// ---------------------------------------------------------------------------
__global__ void f2b_kernel(const float* __restrict__ in, bf16* __restrict__ out, int n4)
{
    int idx = blockIdx.x * blockDim.x + threadIdx.x;
    if (idx >= n4) return;
    float4 v = ((const float4*)in)[idx];
    uint2 o;
    o.x = packbf(v.x, v.y);
    o.y = packbf(v.z, v.w);
    ((uint2*)out)[idx] = o;
}

// ===========================================================================
// bf16 mma.sync GEMM: C[m,n] = act( sum_k A[m,k]*W[n,k] + bias[n] )
// A: MxK bf16 row-major, W: NxK bf16 row-major. Block 256x128, BK=32,
// 256 threads, 8 warps (4m x 2n), warp tile 64x64. 3-stage cp.async pipeline.
// Smem rows: 40 halves (32 data + 8 pad) => all fragment LDS conflict-free.
// ACT: 0=none, 1=silu.  OUTBF: 1 -> write bf16 Cb, 0 -> write fp32 Cf.
// ===========================================================================
#define GS 3
#define A_STG_H (256 * 40)
#define B_STG_H (128 * 40)
#define STG_H (A_STG_H + B_STG_H)
#define GEMM_SMEM_BYTES (GS * STG_H * 2)

template<int ACT, int OUTBF>
__global__ __launch_bounds__(256)
void gemm_bf(const bf16* __restrict__ A, const bf16* __restrict__ W,
             const float* __restrict__ bias, float* __restrict__ Cf,
             bf16* __restrict__ Cb, int M, int N, int K)
{
    extern __shared__ bf16 sm[];
    const int tid = threadIdx.x;
    const int wid = tid >> 5, lane = tid & 31;
    const int g = lane >> 2, tg = lane & 3;
    const int wm = wid >> 1, wn = wid & 1;
    const int row0 = blockIdx.y * 256, col0 = blockIdx.x * 128;
    const uint32_t smb = smem_u32(sm);
    const int NC = K / 32;

    auto issue = [&](int s, int i) {
        const bf16* Ap = A + (size_t)row0 * K + i * 32;
        const bf16* Wp = W + (size_t)col0 * K + i * 32;
        uint32_t aB = smb + (uint32_t)(s * STG_H) * 2;
        uint32_t bB = aB + A_STG_H * 2;
#pragma unroll
        for (int it = 0; it < 4; it++) {
            int f = tid + it * 256, r = f >> 2, ch = f & 3;
            CP16(aB + (uint32_t)(r * 40 + ch * 8) * 2, Ap + (size_t)r * K + ch * 8);
        }
#pragma unroll
        for (int it = 0; it < 2; it++) {
            int f = tid + it * 256, r = f >> 2, ch = f & 3;
            CP16(bB + (uint32_t)(r * 40 + ch * 8) * 2, Wp + (size_t)r * K + ch * 8);
        }
    };

    float acc[4][8][4];
#pragma unroll
    for (int a0 = 0; a0 < 4; a0++)
#pragma unroll
        for (int b0 = 0; b0 < 8; b0++)
#pragma unroll
            for (int c0 = 0; c0 < 4; c0++) acc[a0][b0][c0] = 0.f;

    issue(0, 0); CP_COMMIT();
    issue(1, 1); CP_COMMIT();

    for (int i = 0; i < NC; i++) {
        CP_WAIT1();
        __syncthreads();
        if (i + 2 < NC) issue((i + 2) % GS, i + 2);
        CP_COMMIT();

        const uint32_t* Au = (const uint32_t*)(sm + (i % GS) * STG_H);
        const uint32_t* Bu = (const uint32_t*)(sm + (i % GS) * STG_H + A_STG_H);
#pragma unroll
        for (int ks = 0; ks < 2; ks++) {
            uint32_t af[4][4], bfr[8][2];
#pragma unroll
            for (int mt = 0; mt < 4; mt++) {
                int m = wm * 64 + mt * 16;
                af[mt][0] = Au[(m + g)     * 20 + ks * 8 + tg];
                af[mt][1] = Au[(m + g + 8) * 20 + ks * 8 + tg];
                af[mt][2] = Au[(m + g)     * 20 + ks * 8 + tg + 4];
                af[mt][3] = Au[(m + g + 8) * 20 + ks * 8 + tg + 4];
            }
#pragma unroll
            for (int nt = 0; nt < 8; nt++) {
                int n = wn * 64 + nt * 8;
                bfr[nt][0] = Bu[(n + g) * 20 + ks * 8 + tg];
                bfr[nt][1] = Bu[(n + g) * 20 + ks * 8 + tg + 4];
            }
#pragma unroll
            for (int mt = 0; mt < 4; mt++)
#pragma unroll
                for (int nt = 0; nt < 8; nt++)
                    mma_bf(acc[mt][nt], af[mt], bfr[nt]);
        }
        __syncthreads();
    }

    // epilogue
#pragma unroll
    for (int mt = 0; mt < 4; mt++) {
        int r_ = row0 + wm * 64 + mt * 16 + g;
#pragma unroll
        for (int nt = 0; nt < 8; nt++) {
            int cl = col0 + wn * 64 + nt * 8 + tg * 2;
            float b0 = bias ? bias[cl] : 0.f;
            float b1 = bias ? bias[cl + 1] : 0.f;
            float v0 = acc[mt][nt][0] + b0, v1 = acc[mt][nt][1] + b1;
            float v2 = acc[mt][nt][2] + b0, v3 = acc[mt][nt][3] + b1;
            if (ACT == 1) {
                v0 = v0 / (1.f + __expf(-v0)); v1 = v1 / (1.f + __expf(-v1));
                v2 = v2 / (1.f + __expf(-v2)); v3 = v3 / (1.f + __expf(-v3));
            }
            if (OUTBF) {
                *(uint32_t*)&Cb[(size_t)r_ * N + cl]       = packbf(v0, v1);
                *(uint32_t*)&Cb[(size_t)(r_ + 8) * N + cl] = packbf(v2, v3);
            } else {
                *(float2*)&Cf[(size_t)r_ * N + cl]       = make_float2(v0, v1);
                *(float2*)&Cf[(size_t)(r_ + 8) * N + cl] = make_float2(v2, v3);
            }
        }
    }
}

// ---------------------------------------------------------------------------
// Depthwise conv (KS=3, same-pad along L) + dw bias, bf16 in/out, fp32 math
// ---------------------------------------------------------------------------
__device__ __forceinline__ void unpack4(uint2 u, float* f) {
    bf162 p0 = *(bf162*)&u.x;
    bf162 p1 = *(bf162*)&u.y;
    f[0] = __bfloat162float(p0.x); f[1] = __bfloat162float(p0.y);
    f[2] = __bfloat162float(p1.x); f[3] = __bfloat162float(p1.y);
}

__global__ void dwconv_bf(const bf16* __restrict__ in, const float* __restrict__ w,
                          const float* __restrict__ bias, bf16* __restrict__ out,
                          int L, int C, int total4)
{
    int idx = blockIdx.x * blockDim.x + threadIdx.x;
    if (idx >= total4) return;
    int n4 = C >> 2;
    int c4 = (idx % n4) * 4;
    int l  = (idx / n4) % L;

    float cu[4], r[4];
    unpack4(((const uint2*)in)[idx], cu);
#pragma unroll
    for (int j = 0; j < 4; j++)
        r[j] = fmaf(cu[j], w[(c4 + j) * 3 + 1], bias[c4 + j]);
    if (l > 0) {
        float pv[4];
        unpack4(((const uint2*)in)[idx - n4], pv);
#pragma unroll
        for (int j = 0; j < 4; j++)
            r[j] = fmaf(pv[j], w[(c4 + j) * 3 + 0], r[j]);
    }
    if (l < L - 1) {
        float nv[4];
        unpack4(((const uint2*)in)[idx + n4], nv);
#pragma unroll
        for (int j = 0; j < 4; j++)
            r[j] = fmaf(nv[j], w[(c4 + j) * 3 + 2], r[j]);
    }
    uint2 o;
    o.x = packbf(r[0], r[1]);
    o.y = packbf(r[2], r[3]);
    ((uint2*)out)[idx] = o;
}

// ---------------------------------------------------------------------------
// L2 norm over contiguous 64-half vectors (one warp per vector), in-place bf16.
// applyTemp folds 1/temperature into the scale.
// ---------------------------------------------------------------------------
__global__ void l2norm_bf(bf16* __restrict__ x, const float* __restrict__ tptr,
                          int nvec, int applyTemp)
{
    int vec = blockIdx.x * (blockDim.x >> 5) + (threadIdx.x >> 5);
    if (vec >= nvec) return;
    int lane = threadIdx.x & 31;
    uint32_t* p = (uint32_t*)(x + (size_t)vec * 64);
    uint32_t u = p[lane];
    bf162 h = *(bf162*)&u;
    float a = __bfloat162float(h.x), b = __bfloat162float(h.y);
    float s = fmaf(a, a, b * b);
#pragma unroll
    for (int o = 16; o; o >>= 1) s += __shfl_xor_sync(0xffffffffu, s, o);
    float n = fmaxf(sqrtf(s), 1e-12f);
    float inv = 1.0f / n;
    if (applyTemp) inv *= (1.0f / tptr[0]);
    p[lane] = packbf(a * inv, b * inv);
}

// ---------------------------------------------------------------------------
// Polynomial exp for |x| <= ~0.35
// ---------------------------------------------------------------------------
__device__ __forceinline__ float exp_small(float x)
{
    float p = 1.f / 720.f;
    p = fmaf(p, x, 1.f / 120.f);
    p = fmaf(p, x, 1.f / 24.f);
    p = fmaf(p, x, 1.f / 6.f);
    p = fmaf(p, x, 0.5f);
    p = fmaf(p, x, 1.f);
    p = fmaf(p, x, 1.f);
    return p;
}

// ===========================================================================
// Attention (bf16 m16n8k16): per (b,h), O = softmax(q k^T) v + x residual.
// 128 queries/block, 32-key tiles, 256 threads = 8 warps, each warp 16 rows.
// Smem word strides: sQ/sK 36 (==4 mod 32), sVt/sP 20 (==20 mod 32):
// both make g*stride+tg a bijection mod 32 -> conflict-free fragment LDS.
// ===========================================================================
__global__ __launch_bounds__(256)
void attn_bf(const bf16* __restrict__ Q, const bf16* __restrict__ Kd,
             const bf16* __restrict__ V, const float* __restrict__ X,
             float* __restrict__ O, int L, int C, int H)
{
    __shared__ bf16 sQ[128 * 72];
    __shared__ bf16 sK[32 * 72];
    __shared__ bf16 sVt[64 * 40];
    __shared__ bf16 sP[128 * 40];

    const int b = blockIdx.y / H;
    const int h = blockIdx.y % H;
    const size_t base = (size_t)b * L * C + (size_t)h * HDIM;
    const int q0 = blockIdx.x * 128;

    const int tid = threadIdx.x;
    const int wid = tid >> 5, lane = tid & 31;
    const int g = lane >> 2, tg = lane & 3;
    const int qw = wid * 16;

    // stage Q (128 x 64 halves)
#pragma unroll
    for (int it = 0; it < 4; it++) {
        int f = tid + it * 256, q = f >> 3, ch = f & 7;
        *(uint4*)&sQ[q * 72 + ch * 8] =
            *(const uint4*)&Q[base + (size_t)(q0 + q) * C + ch * 8];
    }

    float Oacc[8][4];
#pragma unroll
    for (int i = 0; i < 8; i++)
#pragma unroll
        for (int j = 0; j < 4; j++) Oacc[i][j] = 0.f;
    float den0 = 0.f, den1 = 0.f;

    const uint32_t* Qu = (const uint32_t*)sQ;
    const uint32_t* Ku = (const uint32_t*)sK;
    const uint32_t* Vtu = (const uint32_t*)sVt;
    uint32_t* Pu = (uint32_t*)sP;

    const int nkt = L / 32;
    for (int kt = 0; kt < nkt; kt++) {
        const int k0 = kt * 32;
        __syncthreads();   // protect prior sK/sVt reads (also orders Q on kt=0)
        // stage K (32 x 64 halves)
        {
            int j = tid >> 3, ch = tid & 7;
            *(uint4*)&sK[j * 72 + ch * 8] =
                *(const uint4*)&Kd[base + (size_t)(k0 + j) * C + ch * 8];
        }
        // stage V transposed: sVt[d][j]
#pragma unroll
        for (int it = 0; it < 2; it++) {
            int f = tid + it * 256, j = f >> 4, c = (f & 15) * 4;
            uint2 vv = *(const uint2*)&V[base + (size_t)(k0 + j) * C + c];
            bf162 p0 = *(bf162*)&vv.x;
            bf162 p1 = *(bf162*)&vv.y;
            sVt[(c + 0) * 40 + j] = p0.x;
            sVt[(c + 1) * 40 + j] = p0.y;
            sVt[(c + 2) * 40 + j] = p1.x;
            sVt[(c + 3) * 40 + j] = p1.y;
        }
        __syncthreads();

        // ---- S = Q K^T  (m16 x n32, k=64) ----
        float sAcc[4][4];
#pragma unroll
        for (int nt = 0; nt < 4; nt++)
#pragma unroll
            for (int j = 0; j < 4; j++) sAcc[nt][j] = 0.f;

#pragma unroll
        for (int ks = 0; ks < 4; ks++) {
            uint32_t a[4];
            a[0] = Qu[(qw + g)     * 36 + ks * 8 + tg];
            a[1] = Qu[(qw + g + 8) * 36 + ks * 8 + tg];
            a[2] = Qu[(qw + g)     * 36 + ks * 8 + tg + 4];
            a[3] = Qu[(qw + g + 8) * 36 + ks * 8 + tg + 4];
#pragma unroll
            for (int nt = 0; nt < 4; nt++) {
                uint32_t bb[2];
                bb[0] = Ku[(nt * 8 + g) * 36 + ks * 8 + tg];
                bb[1] = Ku[(nt * 8 + g) * 36 + ks * 8 + tg + 4];
                mma_bf(sAcc[nt], a, bb);
            }
        }

        // ---- P = exp(S), partial row sums, store bf16 P ----
#pragma unroll
        for (int nt = 0; nt < 4; nt++) {
            float p0 = exp_small(sAcc[nt][0]);
            float p1 = exp_small(sAcc[nt][1]);
            float p2 = exp_small(sAcc[nt][2]);
            float p3 = exp_small(sAcc[nt][3]);
            den0 += p0 + p1;
            den1 += p2 + p3;
            Pu[(qw + g)     * 20 + nt * 4 + tg] = packbf(p0, p1);
            Pu[(qw + g + 8) * 20 + nt * 4 + tg] = packbf(p2, p3);
        }
        __syncwarp();   // sP rows are warp-private

        // ---- O += P V  (m16 x n64, k=32) ----
#pragma unroll
        for (int ks = 0; ks < 2; ks++) {
            uint32_t a[4];
            a[0] = Pu[(qw + g)     * 20 + ks * 8 + tg];
            a[1] = Pu[(qw + g + 8) * 20 + ks * 8 + tg];
            a[2] = Pu[(qw + g)     * 20 + ks * 8 + tg + 4];
            a[3] = Pu[(qw + g + 8) * 20 + ks * 8 + tg + 4];
#pragma unroll
            for (int nt = 0; nt < 8; nt++) {
                uint32_t bb[2];
                bb[0] = Vtu[(nt * 8 + g) * 20 + ks * 8 + tg];
                bb[1] = Vtu[(nt * 8 + g) * 20 + ks * 8 + tg + 4];
                mma_bf(Oacc[nt], a, bb);
            }
        }
        __syncwarp();
    }

    // denominator: reduce across the 4 lanes sharing a groupID
    den0 += __shfl_xor_sync(0xffffffffu, den0, 1);
    den0 += __shfl_xor_sync(0xffffffffu, den0, 2);
    den1 += __shfl_xor_sync(0xffffffffu, den1, 1);
    den1 += __shfl_xor_sync(0xffffffffu, den1, 2);
    const float inv0 = 1.f / den0;
    const float inv1 = 1.f / den1;

    // epilogue: O/den + residual X (fp32)
#pragma unroll
    for (int nt = 0; nt < 8; nt++) {
        int col = h * HDIM + nt * 8 + tg * 2;
        int r0_ = q0 + qw + g;
        size_t off0 = ((size_t)b * L + r0_) * C + col;
        size_t off1 = ((size_t)b * L + r0_ + 8) * C + col;
        float2 x0 = *(const float2*)&X[off0];
        float2 x1 = *(const float2*)&X[off1];
        float2 o0 = make_float2(fmaf(Oacc[nt][0], inv0, x0.x),
                                fmaf(Oacc[nt][1], inv0, x0.y));
        float2 o1 = make_float2(fmaf(Oacc[nt][2], inv1, x1.x),
                                fmaf(Oacc[nt][3], inv1, x1.y));
        *(float2*)&O[off0] = o0;
        *(float2*)&O[off1] = o1;
    }
}

// ---------------------------------------------------------------------------
// LayerNorm over rows of C=1024, optional fused add; OUTBF selects bf16 out.
// ---------------------------------------------------------------------------
template<int OUTBF>
__global__ __launch_bounds__(256)
void layernorm_k(const float* __restrict__ in, const float* __restrict__ add,
                 const float* __restrict__ g, const float* __restrict__ bta,
                 float* __restrict__ outf, bf16* __restrict__ outb, int C)
{
    int row = blockIdx.x;
    int t = threadIdx.x;
    float4 v = ((const float4*)(in + (size_t)row * C))[t];
    if (add) {
        float4 a = ((const float4*)(add + (size_t)row * C))[t];
        v.x += a.x; v.y += a.y; v.z += a.z; v.w += a.w;
    }
    float s  = v.x + v.y + v.z + v.w;
    float s2 = fmaf(v.x, v.x, fmaf(v.y, v.y, fmaf(v.z, v.z, v.w * v.w)));

    __shared__ float red[2][8];
#pragma unroll
    for (int o = 16; o; o >>= 1) {
        s  += __shfl_xor_sync(0xffffffffu, s, o);
        s2 += __shfl_xor_sync(0xffffffffu, s2, o);
    }
    int wid = t >> 5, lane = t & 31;
    if (lane == 0) { red[0][wid] = s; red[1][wid] = s2; }
    __syncthreads();
    if (t < 32) {
        float a  = (lane < 8) ? red[0][lane] : 0.f;
        float b2 = (lane < 8) ? red[1][lane] : 0.f;
#pragma unroll
        for (int o = 4; o; o >>= 1) {
            a  += __shfl_xor_sync(0xffffffffu, a, o);
            b2 += __shfl_xor_sync(0xffffffffu, b2, o);
        }
        if (lane == 0) { red[0][0] = a; red[1][0] = b2; }
    }
    __syncthreads();
    float mean = red[0][0] / C;
    float var  = red[1][0] / C - mean * mean;
    float inv  = rsqrtf(var + 1e-5f);

    float4 gg = ((const float4*)g)[t];
    float4 bb = ((const float4*)bta)[t];
    float o0 = fmaf((v.x - mean) * inv, gg.x, bb.x);
    float o1 = fmaf((v.y - mean) * inv, gg.y, bb.y);
    float o2 = fmaf((v.z - mean) * inv, gg.z, bb.z);
    float o3 = fmaf((v.w - mean) * inv, gg.w, bb.w);
    if (OUTBF) {
        uint2 u;
        u.x = packbf(o0, o1);
        u.y = packbf(o2, o3);
        ((uint2*)(outb + (size_t)row * C))[t] = u;
    } else {
        ((float4*)(outf + (size_t)row * C))[t] = make_float4(o0, o1, o2, o3);
    }
}

// ---------------------------------------------------------------------------
// gated = gp[:, :C] * silu(gp[:, C:])  (bf16 in/out, fp32 math)
// ---------------------------------------------------------------------------
__global__ void gated_bf(const bf16* __restrict__ gp, bf16* __restrict__ out,
                         int M, int C)
{
    int idx = blockIdx.x * blockDim.x + threadIdx.x;
    int n4 = C >> 2;
    if (idx >= M * n4) return;
    int m = idx / n4, c4 = (idx % n4) * 4;
    float val[4], gt[4];
    unpack4(*(const uint2*)&gp[(size_t)m * 2 * C + c4], val);
    unpack4(*(const uint2*)&gp[(size_t)m * 2 * C + C + c4], gt);
    float o[4];
#pragma unroll
    for (int j = 0; j < 4; j++)
        o[j] = val[j] * (gt[j] / (1.f + __expf(-gt[j])));
    uint2 u;
    u.x = packbf(o[0], o[1]);
    u.y = packbf(o[2], o[3]);
    *(uint2*)&out[(size_t)m * C + c4] = u;
}

// ---------------------------------------------------------------------------
// Launch
// ---------------------------------------------------------------------------
extern "C" void kernel_launch(void* const* d_in, const int* in_sizes, int n_in,
                              void* d_out, int out_size)
{
    const float* x       = (const float*)d_in[0];
    const float* wq      = (const float*)d_in[1];
    const float* wk      = (const float*)d_in[2];
    const float* wv      = (const float*)d_in[3];
    const float* q_dw_w  = (const float*)d_in[4];
    const float* q_dw_b  = (const float*)d_in[5];
    const float* q_pw_w  = (const float*)d_in[6];
    const float* q_pw_b  = (const float*)d_in[7];
    const float* k_dw_w  = (const float*)d_in[8];
    const float* k_dw_b  = (const float*)d_in[9];
    const float* k_pw_w  = (const float*)d_in[10];
    const float* k_pw_b  = (const float*)d_in[11];
    const float* v_dw_w  = (const float*)d_in[12];
    const float* v_dw_b  = (const float*)d_in[13];
    const float* v_pw_w  = (const float*)d_in[14];
    const float* v_pw_b  = (const float*)d_in[15];
    const float* gn_g    = (const float*)d_in[16];
    const float* gn_b    = (const float*)d_in[17];
    const float* w_gate  = (const float*)d_in[18];
    const float* w_out   = (const float*)d_in[19];
    const float* b_out   = (const float*)d_in[20];
    const float* temp    = (const float*)d_in[21];
    const float* fn_g    = (const float*)d_in[22];
    const float* fn_b    = (const float*)d_in[23];
    float* out = (float*)d_out;

    const int C = DIM;
    const int L = SEQ;
    const int M = in_sizes[0] / C;     // 4096
    const int B = M / L;               // 2
    const int H = NHEADS;

    bf16 *bx, *bwq, *bwk, *bwv, *bqpw, *bkpw, *bvpw, *bwg, *bwo;
    bf16 *bt1, *bt2, *bq, *bk, *bv, *bnrm, *bgp, *bgated;
    float *attn, *go;
    cudaGetSymbolAddress((void**)&bx,   b_x);
    cudaGetSymbolAddress((void**)&bwq,  b_wq);
    cudaGetSymbolAddress((void**)&bwk,  b_wk);
    cudaGetSymbolAddress((void**)&bwv,  b_wv);
    cudaGetSymbolAddress((void**)&bqpw, b_qpw);
    cudaGetSymbolAddress((void**)&bkpw, b_kpw);
    cudaGetSymbolAddress((void**)&bvpw, b_vpw);
    cudaGetSymbolAddress((void**)&bwg,  b_wg);
    cudaGetSymbolAddress((void**)&bwo,  b_wo);
    cudaGetSymbolAddress((void**)&bt1,  b_t1);
    cudaGetSymbolAddress((void**)&bt2,  b_t2);
    cudaGetSymbolAddress((void**)&bq,   b_q);
    cudaGetSymbolAddress((void**)&bk,   b_k);
    cudaGetSymbolAddress((void**)&bv,   b_v);
    cudaGetSymbolAddress((void**)&bnrm, b_nrm);
    cudaGetSymbolAddress((void**)&bgp,  b_gp);
    cudaGetSymbolAddress((void**)&bgated, b_gated);
    cudaGetSymbolAddress((void**)&attn, g_attn);
    cudaGetSymbolAddress((void**)&go,   g_o);

    cudaFuncSetAttribute((const void*)gemm_bf<1,1>,
                         cudaFuncAttributeMaxDynamicSharedMemorySize, GEMM_SMEM_BYTES);
    cudaFuncSetAttribute((const void*)gemm_bf<0,1>,
                         cudaFuncAttributeMaxDynamicSharedMemorySize, GEMM_SMEM_BYTES);
    cudaFuncSetAttribute((const void*)gemm_bf<0,0>,
                         cudaFuncAttributeMaxDynamicSharedMemorySize, GEMM_SMEM_BYTES);

    // ---- fp32 -> bf16 conversions (input + weights) ----
    {
        int n4 = M * C / 4;
        f2b_kernel<<<(n4 + 255) / 256, 256>>>(x, bx, n4);
        n4 = C * C / 4;
        f2b_kernel<<<(n4 + 255) / 256, 256>>>(wq, bwq, n4);
        f2b_kernel<<<(n4 + 255) / 256, 256>>>(wk, bwk, n4);
        f2b_kernel<<<(n4 + 255) / 256, 256>>>(wv, bwv, n4);
        f2b_kernel<<<(n4 + 255) / 256, 256>>>(q_pw_w, bqpw, n4);
        f2b_kernel<<<(n4 + 255) / 256, 256>>>(k_pw_w, bkpw, n4);
        f2b_kernel<<<(n4 + 255) / 256, 256>>>(v_pw_w, bvpw, n4);
        n4 = 2 * C * C / 4;
        f2b_kernel<<<(n4 + 255) / 256, 256>>>(w_gate, bwg, n4);
        n4 = C * C / 4;
        f2b_kernel<<<(n4 + 255) / 256, 256>>>(w_out, bwo, n4);
    }

    dim3 gThr(256);
    dim3 g1(C / 128, M / 256);            // 8 x 16
    dim3 g2(2 * C / 128, M / 256);        // 16 x 16

    const int total4 = M * C / 4;
    const int dwBlocks = (total4 + 255) / 256;

    // q path
    gemm_bf<1,1><<<g1, gThr, GEMM_SMEM_BYTES>>>(bx, bwq, nullptr, nullptr, bt1, M, C, C);
    dwconv_bf<<<dwBlocks, 256>>>(bt1, q_dw_w, q_dw_b, bt2, L, C, total4);
    gemm_bf<0,1><<<g1, gThr, GEMM_SMEM_BYTES>>>(bt2, bqpw, q_pw_b, nullptr, bq, M, C, C);
    // k path
    gemm_bf<1,1><<<g1, gThr, GEMM_SMEM_BYTES>>>(bx, bwk, nullptr, nullptr, bt1, M, C, C);
    dwconv_bf<<<dwBlocks, 256>>>(bt1, k_dw_w, k_dw_b, bt2, L, C, total4);
    gemm_bf<0,1><<<g1, gThr, GEMM_SMEM_BYTES>>>(bt2, bkpw, k_pw_b, nullptr, bk, M, C, C);
    // v path
    gemm_bf<1,1><<<g1, gThr, GEMM_SMEM_BYTES>>>(bx, bwv, nullptr, nullptr, bt1, M, C, C);
    dwconv_bf<<<dwBlocks, 256>>>(bt1, v_dw_w, v_dw_b, bt2, L, C, total4);
    gemm_bf<0,1><<<g1, gThr, GEMM_SMEM_BYTES>>>(bt2, bvpw, v_pw_b, nullptr, bv, M, C, C);

    // l2norm q (folds 1/temperature) and k
    const int nvec = M * H;
    l2norm_bf<<<nvec / 8, 256>>>(bq, temp, nvec, 1);
    l2norm_bf<<<nvec / 8, 256>>>(bk, temp, nvec, 0);

    // attention + residual
    dim3 ga(L / 128, B * H);
    attn_bf<<<ga, 256>>>(bq, bk, bv, x, attn, L, C, H);

    // group norm -> bf16
    layernorm_k<1><<<M, 256>>>(attn, nullptr, gn_g, gn_b, nullptr, bnrm, C);

    // gate projection, gating, output projection
    gemm_bf<0,1><<<g2, gThr, GEMM_SMEM_BYTES>>>(bnrm, bwg, nullptr, nullptr, bgp, M, 2 * C, C);
    gated_bf<<<(M * C / 4 + 255) / 256, 256>>>(bgp, bgated, M, C);
    gemm_bf<0,0><<<g1, gThr, GEMM_SMEM_BYTES>>>(bgated, bwo, b_out, go, nullptr, M, C, C);

    // final layernorm with fused residual (out + attn_out), fp32 out
    layernorm_k<0><<<M, 256>>>(go, attn, fn_g, fn_b, out, nullptr, C);
}